// round 13
// baseline (speedup 1.0000x reference)
#include <cuda_runtime.h>
#include <cuda_fp16.h>
#include <cstdint>

// Problem constants: B=4096 batch, T=4 tasks, D=1024 dim, L=2 layers, E=4.
#define BB 4096
#define TT 4
#define DD 1024
#define LL 2
#define EE 4

// GEMM tiling: 256 threads, 8 warps (2m x 4n), per-warp 64x32. 2 CTAs/SM.
// Each CTA processes TWO 128x128 m-tiles back-to-back on one cp.async ring.
#define BM 128
#define BN 128
#define KC 64
#define NCHUNK (DD / KC)       // 16 per tile
#define NTOT   (2 * NCHUNK)    // 32 per CTA
#define NSTAGE 3

// SMEM stage: A [128r][128B] = 16KB, W [128r][128B] = 16KB
#define OFF_A 0
#define OFF_W 16384
#define STAGE 32768
#define SMEM_TOTAL (NSTAGE * STAGE)   // 98304 -> two CTAs fit in 228KB

#define SW128(x) ((x) ^ (((x) >> 3) & 0x70))

typedef __half fp16;

// -------- scratch (allocation-free: __device__ globals) --------
__device__ fp16  g_in [TT * BB * DD];        // act in  [T][B][D]
__device__ fp16  g_t1 [TT * BB * DD];        // stage-1 [T][B][D]
__device__ fp16  g_w1 [LL * TT * DD * DD];   // W1' [L][T][n][k]
__device__ fp16  g_w2 [LL * TT * DD * DD];   // W2' [L][T][n][k]
__device__ fp16  g_teo[BB * TT * DD];        // fp16 [B][T][D]

// ---------------------------------------------------------------------------
__device__ __forceinline__ uint32_t smem_u32(const void* p) {
    uint32_t a;
    asm("{ .reg .u64 t; cvta.to.shared.u64 t, %1; cvt.u32.u64 %0, t; }"
        : "=r"(a) : "l"(p));
    return a;
}

__device__ __forceinline__ void ldsm_x4(uint32_t& r0, uint32_t& r1,
                                        uint32_t& r2, uint32_t& r3,
                                        uint32_t addr) {
    asm volatile("ldmatrix.sync.aligned.m8n8.x4.shared.b16 {%0,%1,%2,%3}, [%4];"
                 : "=r"(r0), "=r"(r1), "=r"(r2), "=r"(r3) : "r"(addr));
}

__device__ __forceinline__ void mma_fp16(float* c, const uint32_t* a,
                                         const uint32_t* b) {
    asm volatile(
        "mma.sync.aligned.m16n8k16.row.col.f32.f16.f16.f32 "
        "{%0,%1,%2,%3}, {%4,%5,%6,%7}, {%8,%9}, {%0,%1,%2,%3};"
        : "+f"(c[0]), "+f"(c[1]), "+f"(c[2]), "+f"(c[3])
        : "r"(a[0]), "r"(a[1]), "r"(a[2]), "r"(a[3]), "r"(b[0]), "r"(b[1]));
}

#define CPA16(dst, src) \
    asm volatile("cp.async.cg.shared.global [%0], [%1], 16;" :: "r"(dst), "l"(src))
#define CPCOMMIT() asm volatile("cp.async.commit_group;" ::: "memory")
#define CPWAIT1()  asm volatile("cp.async.wait_group 1;"  ::: "memory")

__device__ __forceinline__ uint32_t pack_h2(float v0, float v1) {
    __half2 h = __floats2half2_rn(v0, v1);
    return *reinterpret_cast<uint32_t*>(&h);
}

// ============================================================================
// prep: x [B][T][D] fp32 -> fp16 [T][B][D] (RN)
// ============================================================================
__global__ __launch_bounds__(256)
void split_act(const float* __restrict__ x, fp16* __restrict__ a)
{
    int p = blockIdx.x * 256 + threadIdx.x;     // pair index
    int d2 = p & (DD / 2 - 1);
    int bt = p >> 9;                            // DD/2 = 512
    int t = bt & (TT - 1);
    int b = bt >> 2;
    float2 v = reinterpret_cast<const float2*>(x)[p];
    size_t o = (((size_t)(t * BB + b) * DD) >> 1) + d2;
    reinterpret_cast<uint32_t*>(a)[o] = pack_h2(v.x, v.y);
}

// ============================================================================
// prep: convert+transpose ALL weights [L][T][k][n] fp32 -> fp16 [L][T][n][k]
// grid.z = LL*TT*2: z -> (layer, which (W1/W2), task)
// ============================================================================
__global__ __launch_bounds__(256)
void conv_w(const float* __restrict__ W1, const float* __restrict__ W2,
            fp16* __restrict__ o1, fp16* __restrict__ o2)
{
    __shared__ float tile[32][33];
    const int z   = blockIdx.z;
    const int t   = z & (TT - 1);
    const int wsel = (z >> 2) & 1;
    const int l   = z >> 3;
    const size_t woff = ((size_t)l * TT + t) * DD * DD;
    const float* Wt = (wsel ? W2 : W1) + woff;
    uint16_t* ot = reinterpret_cast<uint16_t*>(wsel ? o2 : o1) + woff;

    const int k0 = blockIdx.y * 32, n0 = blockIdx.x * 32;
    const int tx = threadIdx.x, ty = threadIdx.y;   // 32 x 8
    #pragma unroll
    for (int i = 0; i < 4; i++)
        tile[ty + i * 8][tx] = Wt[(size_t)(k0 + ty + i * 8) * DD + n0 + tx];
    __syncthreads();
    #pragma unroll
    for (int i = 0; i < 4; i++) {
        int n = n0 + ty + i * 8;
        __half h = __float2half_rn(tile[tx][ty + i * 8]);
        ot[(size_t)n * DD + k0 + tx] = *reinterpret_cast<uint16_t*>(&h);
    }
}

// ============================================================================
// fp16 mma.sync GEMM:  acc = A @ W   (per-warp 64x32, 2 CTAs/SM,
// two m-tiles per CTA chained on one continuous cp.async ring)
// MODE 0: Y = relu(acc + b)            -> fp16 [T][B][D]
// MODE 1: Y = relu(acc + b) * scale    -> fp16 [B][T][D]
// ============================================================================
template <int MODE>
__global__ __launch_bounds__(256, 2)
void gemm_pre(const fp16* __restrict__ Ain, const fp16* __restrict__ Wm,
              const float* __restrict__ bias, const float* __restrict__ inte,
              fp16* __restrict__ Yo)
{
    extern __shared__ char smem[];
    const uint32_t sbase = smem_u32(smem);
    const int tid  = threadIdx.x;
    const int warp = tid >> 5;
    const int lane = tid & 31;
    const int task = blockIdx.z;
    const int m0   = blockIdx.y * (2 * BM);   // this CTA: rows [m0, m0+256)
    const int n0   = blockIdx.x * BN;

    const fp16* ab = Ain + (size_t)(task * BB + m0) * DD;
    const fp16* wb = Wm  + (size_t)(task * DD + n0) * DD;

    const int lrow = tid >> 3;          // 0..31 (per it: +32)
    const int k16  = tid & 7;           // 16B seg within 128B row

    // cc = global chunk 0..31; tile = cc>>4, k0 = (cc&15)*KC
    auto issue = [&](int cc) {
        const int k0 = (cc & (NCHUNK - 1)) * KC;
        const int mb = (cc >> 4) * BM;          // 0 or 128
        const uint32_t stb = sbase + (cc % NSTAGE) * STAGE;
        #pragma unroll
        for (int it = 0; it < 4; it++) {
            const int row = it * 32 + lrow;
            const uint32_t dsw = SW128((uint32_t)(row * 128 + k16 * 16));
            CPA16(stb + OFF_A + dsw, ab + (size_t)(mb + row) * DD + k0 + k16 * 8);
            CPA16(stb + OFF_W + dsw, wb + (size_t)row * DD + k0 + k16 * 8);
        }
    };

    issue(0); CPCOMMIT();
    issue(1); CPCOMMIT();

    float acc[4][4][4];
    #pragma unroll
    for (int i = 0; i < 4; ++i)
        #pragma unroll
        for (int j = 0; j < 4; ++j)
            #pragma unroll
            for (int r = 0; r < 4; ++r) acc[i][j][r] = 0.0f;

    const int wm = warp & 1;    // 64-row group
    const int wn = warp >> 1;   // 32-col group
    const int a_lrow = lane & 15;
    const int a_lcol = (lane >> 4) << 4;
    const int b_row  = ((lane >> 4) & 1) * 8 + (lane & 7);
    const int b_boff = ((lane >> 3) & 1) * 16;

    const float* bt = bias + task * DD;
    const int er = lane >> 2;
    const int ec = (lane & 3) * 2;
    float scale = 1.0f;
    if (MODE == 1 && inte != nullptr) {
        const float* it = inte + task * EE;
        scale = it[0] + it[1] + it[2] + it[3];
    }
    uint32_t* Y32 = reinterpret_cast<uint32_t*>(Yo);

    auto epilogue = [&](int tile) {
        #pragma unroll
        for (int mf = 0; mf < 4; ++mf) {
            const int m = m0 + tile * BM + wm * 64 + mf * 16 + er;
            #pragma unroll
            for (int nf = 0; nf < 4; ++nf) {
                const int n = n0 + wn * 32 + nf * 8 + ec;
                float2 b2 = *reinterpret_cast<const float2*>(bt + n);
                float v0 = fmaxf(acc[mf][nf][0] + b2.x, 0.0f) * scale;
                float v1 = fmaxf(acc[mf][nf][1] + b2.y, 0.0f) * scale;
                float v2 = fmaxf(acc[mf][nf][2] + b2.x, 0.0f) * scale;
                float v3 = fmaxf(acc[mf][nf][3] + b2.y, 0.0f) * scale;
                size_t o0, o1;
                if constexpr (MODE == 0) {          // [T][B][D]
                    o0 = (((size_t)(task * BB + m)     * DD) + n) >> 1;
                    o1 = (((size_t)(task * BB + m + 8) * DD) + n) >> 1;
                } else {                            // [B][T][D]
                    o0 = (((size_t)m       * TT + task) * DD + n) >> 1;
                    o1 = (((size_t)(m + 8) * TT + task) * DD + n) >> 1;
                }
                Y32[o0] = pack_h2(v0, v1);
                Y32[o1] = pack_h2(v2, v3);
                #pragma unroll
                for (int r = 0; r < 4; ++r) acc[mf][nf][r] = 0.0f;
            }
        }
    };

    for (int cc = 0; cc < NTOT; ++cc) {
        CPWAIT1();
        __syncthreads();
        // prefetch stage cc+2 (its buffer was last read in chunk cc-1; every
        // warp passed this barrier, so all cc-1 reads are complete)
        if (cc + 2 < NTOT) issue(cc + 2);
        CPCOMMIT();

        const uint32_t stb = sbase + (cc % NSTAGE) * STAGE;

        #pragma unroll
        for (int ks = 0; ks < 4; ++ks) {
            uint32_t ah[4][4], bh[4][2];
            #pragma unroll
            for (int mf = 0; mf < 4; ++mf) {
                uint32_t off = SW128((uint32_t)(
                    (wm * 64 + mf * 16 + a_lrow) * 128 + ks * 32 + a_lcol));
                ldsm_x4(ah[mf][0], ah[mf][1], ah[mf][2], ah[mf][3],
                        stb + OFF_A + off);
            }
            #pragma unroll
            for (int nfp = 0; nfp < 2; ++nfp) {
                uint32_t off = SW128((uint32_t)(
                    (wn * 32 + nfp * 16 + b_row) * 128 + ks * 32 + b_boff));
                ldsm_x4(bh[2*nfp][0], bh[2*nfp][1], bh[2*nfp+1][0], bh[2*nfp+1][1],
                        stb + OFF_W + off);
            }
            #pragma unroll
            for (int mf = 0; mf < 4; ++mf)
                #pragma unroll
                for (int nf = 0; nf < 4; ++nf)
                    mma_fp16(acc[mf][nf], ah[mf], bh[nf]);
        }

        // tile-0 epilogue runs while tile-1's first chunks are in flight
        if (cc == NCHUNK - 1) epilogue(0);
    }
    epilogue(1);
}

// ============================================================================
// Gate + combine: 2 batch rows per block, 256 threads. teo: fp16 [B][T][D].
// Output: fp32 [B][T][D] (outf) OR fp16 [T][B][D] (outh).
// ============================================================================
__global__ __launch_bounds__(256)
void gate_combine(const fp16* __restrict__ teo, const float* __restrict__ Wg,
                  const float* __restrict__ bg, float* __restrict__ outf,
                  fp16* __restrict__ outh)
{
    __shared__ float s_teo[2][TT][DD];   // 32 KB
    __shared__ float s_g[2][TT][TT];

    const int tid  = threadIdx.x;
    const int half = tid >> 7;            // 0 or 1 -> batch row
    const int htid = tid & 127;
    const int warp = htid >> 5;           // 0..3 (task row within half)
    const int lane = tid & 31;

    const int b = blockIdx.x * 2 + half;
    const size_t base = (size_t)b * TT * DD;
    const uint32_t* t16 = reinterpret_cast<const uint32_t*>(teo) + (base >> 1);
    for (int idx = htid; idx < TT * DD / 2; idx += 128) {
        __half2 h = *reinterpret_cast<const __half2*>(t16 + idx);
        float2 f = __half22float2(h);
        s_teo[half][0][idx * 2]     = f.x;
        s_teo[half][0][idx * 2 + 1] = f.y;
    }
    __syncthreads();

    float a0 = 0.f, a1 = 0.f, a2 = 0.f, a3 = 0.f;
    for (int d = lane; d < DD; d += 32) {
        float v = s_teo[half][warp][d];
        float4 w = reinterpret_cast<const float4*>(Wg)[d];
        a0 = fmaf(v, w.x, a0);
        a1 = fmaf(v, w.y, a1);
        a2 = fmaf(v, w.z, a2);
        a3 = fmaf(v, w.w, a3);
    }
    #pragma unroll
    for (int off = 16; off; off >>= 1) {
        a0 += __shfl_xor_sync(0xffffffffu, a0, off);
        a1 += __shfl_xor_sync(0xffffffffu, a1, off);
        a2 += __shfl_xor_sync(0xffffffffu, a2, off);
        a3 += __shfl_xor_sync(0xffffffffu, a3, off);
    }
    if (lane == 0) {
        float l0 = a0 + bg[0], l1 = a1 + bg[1], l2 = a2 + bg[2], l3 = a3 + bg[3];
        float m = fmaxf(fmaxf(l0, l1), fmaxf(l2, l3));
        float e0 = __expf(l0 - m), e1 = __expf(l1 - m);
        float e2 = __expf(l2 - m), e3 = __expf(l3 - m);
        float inv = 1.0f / (e0 + e1 + e2 + e3);
        s_g[half][warp][0] = e0 * inv;
        s_g[half][warp][1] = e1 * inv;
        s_g[half][warp][2] = e2 * inv;
        s_g[half][warp][3] = e3 * inv;
    }
    __syncthreads();

    #pragma unroll
    for (int t = 0; t < TT; t++) {
        const float g0 = s_g[half][t][0], g1 = s_g[half][t][1];
        const float g2 = s_g[half][t][2], g3 = s_g[half][t][3];
        for (int d2 = htid; d2 < DD / 2; d2 += 128) {
            const int d = d2 * 2;
            float r0 = s_teo[half][t][d], r1 = s_teo[half][t][d + 1];
            r0 = fmaf(g0, s_teo[half][0][d], r0);  r1 = fmaf(g0, s_teo[half][0][d+1], r1);
            r0 = fmaf(g1, s_teo[half][1][d], r0);  r1 = fmaf(g1, s_teo[half][1][d+1], r1);
            r0 = fmaf(g2, s_teo[half][2][d], r0);  r1 = fmaf(g2, s_teo[half][2][d+1], r1);
            r0 = fmaf(g3, s_teo[half][3][d], r0);  r1 = fmaf(g3, s_teo[half][3][d+1], r1);
            if (outf != nullptr) {
                float2 v; v.x = r0; v.y = r1;
                *reinterpret_cast<float2*>(outf + base + (size_t)t * DD + d) = v;
            } else {
                size_t o = (((size_t)(t * BB + b) * DD) + d) >> 1;
                reinterpret_cast<uint32_t*>(outh)[o] = pack_h2(r0, r1);
            }
        }
    }
}

// ============================================================================
// launch
// ============================================================================
extern "C" void kernel_launch(void* const* d_in, const int* in_sizes, int n_in,
                              void* d_out, int out_size)
{
    const float* x    = (const float*)d_in[0];
    const float* W1   = (const float*)d_in[1];
    const float* b1   = (const float*)d_in[2];
    const float* W2   = (const float*)d_in[3];
    const float* b2   = (const float*)d_in[4];
    const float* inte = (const float*)d_in[5];
    const float* Wg   = (const float*)d_in[6];
    const float* bg   = (const float*)d_in[7];
    float* out = (float*)d_out;

    cudaFuncSetAttribute(gemm_pre<0>, cudaFuncAttributeMaxDynamicSharedMemorySize,
                         SMEM_TOTAL);
    cudaFuncSetAttribute(gemm_pre<1>, cudaFuncAttributeMaxDynamicSharedMemorySize,
                         SMEM_TOTAL);

    fp16 *ain, *t1, *w1, *w2, *teo;
    cudaGetSymbolAddress((void**)&ain, g_in);
    cudaGetSymbolAddress((void**)&t1,  g_t1);
    cudaGetSymbolAddress((void**)&w1,  g_w1);
    cudaGetSymbolAddress((void**)&w2,  g_w2);
    cudaGetSymbolAddress((void**)&teo, g_teo);

    split_act<<<(BB * TT * DD / 2) / 256, 256>>>(x, ain);

    // Convert ALL layers' weights in one launch.
    dim3 wgrid(DD / 32, DD / 32, LL * TT * 2);    // (32, 32, 16)
    dim3 wblk(32, 8);
    conv_w<<<wgrid, wblk>>>(W1, W2, w1, w2);

    dim3 ggrid(DD / BN, BB / (2 * BM), TT);       // (8, 16, 4) = 512 CTAs

    for (int l = 0; l < LL; l++) {
        const fp16*  w1l = w1 + (size_t)l * TT * DD * DD;
        const fp16*  w2l = w2 + (size_t)l * TT * DD * DD;
        const float* b1l = b1 + (size_t)l * TT * DD;
        const float* b2l = b2 + (size_t)l * TT * DD;
        const float* il  = inte + (size_t)l * TT * EE;
        const float* Wgl = Wg + (size_t)l * DD * TT;
        const float* bgl = bg + (size_t)l * TT;

        gemm_pre<0><<<ggrid, 256, SMEM_TOTAL>>>(ain, w1l, b1l, nullptr, t1);
        gemm_pre<1><<<ggrid, 256, SMEM_TOTAL>>>(t1, w2l, b2l, il, teo);

        if (l == LL - 1)
            gate_combine<<<BB / 2, 256>>>(teo, Wgl, bgl, out, nullptr);
        else
            gate_combine<<<BB / 2, 256>>>(teo, Wgl, bgl, nullptr, ain);
    }
}

// round 14
// speedup vs baseline: 1.2226x; 1.2226x over previous
#include <cuda_runtime.h>
#include <cuda_fp16.h>
#include <cstdint>

// Problem constants: B=4096 batch, T=4 tasks, D=1024 dim, L=2 layers, E=4.
#define BB 4096
#define TT 4
#define DD 1024
#define LL 2
#define EE 4

// GEMM tiling: 256 threads, 8 warps (2m x 4n), per-warp 64x32. 2 CTAs/SM.
#define BM 128
#define BN 128
#define KC 64
#define NCHUNK (DD / KC)   // 16
#define NSTAGE 3

// SMEM stage: A [128r][128B] = 16KB, W [128r][128B] = 16KB
#define OFF_A 0
#define OFF_W 16384
#define STAGE 32768
#define SMEM_TOTAL (NSTAGE * STAGE)   // 98304 -> two CTAs fit in 228KB

#define SW128(x) ((x) ^ (((x) >> 3) & 0x70))

typedef __half fp16;

// -------- scratch (allocation-free: __device__ globals) --------
__device__ fp16  g_in [TT * BB * DD];        // act in  [T][B][D]
__device__ fp16  g_t1 [TT * BB * DD];        // stage-1 [T][B][D]
__device__ fp16  g_w1 [LL * TT * DD * DD];   // W1' [L][T][n][k]
__device__ fp16  g_w2 [LL * TT * DD * DD];   // W2' [L][T][n][k]
__device__ fp16  g_teo[BB * TT * DD];        // fp16 [B][T][D]

// ---------------------------------------------------------------------------
__device__ __forceinline__ uint32_t smem_u32(const void* p) {
    uint32_t a;
    asm("{ .reg .u64 t; cvta.to.shared.u64 t, %1; cvt.u32.u64 %0, t; }"
        : "=r"(a) : "l"(p));
    return a;
}

__device__ __forceinline__ void ldsm_x4(uint32_t& r0, uint32_t& r1,
                                        uint32_t& r2, uint32_t& r3,
                                        uint32_t addr) {
    asm volatile("ldmatrix.sync.aligned.m8n8.x4.shared.b16 {%0,%1,%2,%3}, [%4];"
                 : "=r"(r0), "=r"(r1), "=r"(r2), "=r"(r3) : "r"(addr));
}

__device__ __forceinline__ void mma_fp16(float* c, const uint32_t* a,
                                         const uint32_t* b) {
    asm volatile(
        "mma.sync.aligned.m16n8k16.row.col.f32.f16.f16.f32 "
        "{%0,%1,%2,%3}, {%4,%5,%6,%7}, {%8,%9}, {%0,%1,%2,%3};"
        : "+f"(c[0]), "+f"(c[1]), "+f"(c[2]), "+f"(c[3])
        : "r"(a[0]), "r"(a[1]), "r"(a[2]), "r"(a[3]), "r"(b[0]), "r"(b[1]));
}

#define CPA16(dst, src) \
    asm volatile("cp.async.cg.shared.global [%0], [%1], 16;" :: "r"(dst), "l"(src))
#define CPCOMMIT() asm volatile("cp.async.commit_group;" ::: "memory")
#define CPWAIT1()  asm volatile("cp.async.wait_group 1;"  ::: "memory")

__device__ __forceinline__ uint32_t pack_h2(float v0, float v1) {
    __half2 h = __floats2half2_rn(v0, v1);
    return *reinterpret_cast<uint32_t*>(&h);
}

// ============================================================================
// prep (merged): blocks [0, WBLK) convert+transpose weights; blocks
// [WBLK, WBLK+ABLK) convert activations. All blocks 256 threads.
//   weights: [L][T][k][n] fp32 -> fp16 [L][T][n][k]
//   acts:    x [B][T][D] fp32 -> fp16 [T][B][D]
// ============================================================================
#define WBLK (32 * 32 * LL * TT * 2)          // 16384 weight-tile blocks
#define ABLK ((BB * TT * DD / 2) / 256)       // 32768 activation blocks

__global__ __launch_bounds__(256)
void prep_all(const float* __restrict__ x,
              const float* __restrict__ W1, const float* __restrict__ W2,
              fp16* __restrict__ xa,
              fp16* __restrict__ o1, fp16* __restrict__ o2)
{
    const int bid = blockIdx.x;
    if (bid < WBLK) {
        // ---- weight convert+transpose: decode (z, ky, nx) ----
        __shared__ float tile[32][33];
        const int z  = bid >> 10;            // 0..15
        const int ky = (bid >> 5) & 31;
        const int nx = bid & 31;
        const int t    = z & (TT - 1);
        const int wsel = (z >> 2) & 1;
        const int l    = z >> 3;
        const size_t woff = ((size_t)l * TT + t) * DD * DD;
        const float* Wt = (wsel ? W2 : W1) + woff;
        uint16_t* ot = reinterpret_cast<uint16_t*>(wsel ? o2 : o1) + woff;

        const int k0 = ky * 32, n0 = nx * 32;
        const int tx = threadIdx.x & 31, ty = threadIdx.x >> 5;   // 32 x 8
        #pragma unroll
        for (int i = 0; i < 4; i++)
            tile[ty + i * 8][tx] = Wt[(size_t)(k0 + ty + i * 8) * DD + n0 + tx];
        __syncthreads();
        #pragma unroll
        for (int i = 0; i < 4; i++) {
            int n = n0 + ty + i * 8;
            __half h = __float2half_rn(tile[tx][ty + i * 8]);
            ot[(size_t)n * DD + k0 + tx] = *reinterpret_cast<uint16_t*>(&h);
        }
    } else {
        // ---- activation convert ----
        int p = (bid - WBLK) * 256 + threadIdx.x;   // pair index
        int d2 = p & (DD / 2 - 1);
        int bt = p >> 9;                            // DD/2 = 512
        int t = bt & (TT - 1);
        int b = bt >> 2;
        float2 v = reinterpret_cast<const float2*>(x)[p];
        size_t o = (((size_t)(t * BB + b) * DD) >> 1) + d2;
        reinterpret_cast<uint32_t*>(xa)[o] = pack_h2(v.x, v.y);
    }
}

// ============================================================================
// fp16 mma.sync GEMM:  acc = A @ W   (per-warp 64x32 tile, 2 CTAs/SM)
// Mainloop = round-12 structure (measured best); stage bases rotate in regs.
// MODE 0: Y = relu(acc + b)            -> fp16 [T][B][D]
// MODE 1: Y = relu(acc + b) * scale    -> fp16 [B][T][D]
// ============================================================================
template <int MODE>
__global__ __launch_bounds__(256, 2)
void gemm_pre(const fp16* __restrict__ Ain, const fp16* __restrict__ Wm,
              const float* __restrict__ bias, const float* __restrict__ inte,
              fp16* __restrict__ Yo)
{
    extern __shared__ char smem[];
    const uint32_t sbase = smem_u32(smem);
    const int tid  = threadIdx.x;
    const int warp = tid >> 5;
    const int lane = tid & 31;
    const int task = blockIdx.z;
    const int m0   = blockIdx.y * BM;
    const int n0   = blockIdx.x * BN;

    const fp16* ab = Ain + (size_t)(task * BB + m0) * DD;
    const fp16* wb = Wm  + (size_t)(task * DD + n0) * DD;

    const int lrow = tid >> 3;          // 0..31 (per it: +32)
    const int k16  = tid & 7;           // 16B seg within 128B row

    auto issue = [&](int k0, uint32_t stb) {
        #pragma unroll
        for (int it = 0; it < 4; it++) {
            const int row = it * 32 + lrow;
            const uint32_t dsw = SW128((uint32_t)(row * 128 + k16 * 16));
            const size_t so = (size_t)row * DD + k0 + k16 * 8;
            CPA16(stb + OFF_A + dsw, ab + so);
            CPA16(stb + OFF_W + dsw, wb + so);
        }
    };

    // rotating stage bases (avoids % NSTAGE)
    uint32_t st_cur = sbase;                 // stage of chunk c
    uint32_t st_nx1 = sbase + STAGE;         // stage of chunk c+1
    uint32_t st_nx2 = sbase + 2 * STAGE;     // stage of chunk c+2

    issue(0, st_cur); CPCOMMIT();
    issue(KC, st_nx1); CPCOMMIT();

    float acc[4][4][4];
    #pragma unroll
    for (int i = 0; i < 4; ++i)
        #pragma unroll
        for (int j = 0; j < 4; ++j)
            #pragma unroll
            for (int r = 0; r < 4; ++r) acc[i][j][r] = 0.0f;

    const int wm = warp & 1;    // 64-row group
    const int wn = warp >> 1;   // 32-col group
    const int a_lrow = lane & 15;
    const int a_lcol = (lane >> 4) << 4;
    const int b_row  = ((lane >> 4) & 1) * 8 + (lane & 7);
    const int b_boff = ((lane >> 3) & 1) * 16;

    for (int c = 0; c < NCHUNK; ++c) {
        CPWAIT1();
        __syncthreads();
        // prefetch stage c+2 (its buffer was last read in chunk c-1; every
        // warp passed this barrier, so all c-1 reads are complete)
        if (c + 2 < NCHUNK) issue((c + 2) * KC, st_nx2);
        CPCOMMIT();

        const uint32_t stb = st_cur;

        #pragma unroll
        for (int ks = 0; ks < 4; ++ks) {
            uint32_t ah[4][4], bh[4][2];
            #pragma unroll
            for (int mf = 0; mf < 4; ++mf) {
                uint32_t off = SW128((uint32_t)(
                    (wm * 64 + mf * 16 + a_lrow) * 128 + ks * 32 + a_lcol));
                ldsm_x4(ah[mf][0], ah[mf][1], ah[mf][2], ah[mf][3],
                        stb + OFF_A + off);
            }
            #pragma unroll
            for (int nfp = 0; nfp < 2; ++nfp) {
                uint32_t off = SW128((uint32_t)(
                    (wn * 32 + nfp * 16 + b_row) * 128 + ks * 32 + b_boff));
                ldsm_x4(bh[2*nfp][0], bh[2*nfp][1], bh[2*nfp+1][0], bh[2*nfp+1][1],
                        stb + OFF_W + off);
            }
            #pragma unroll
            for (int mf = 0; mf < 4; ++mf)
                #pragma unroll
                for (int nf = 0; nf < 4; ++nf)
                    mma_fp16(acc[mf][nf], ah[mf], bh[nf]);
        }

        // rotate stage bases
        uint32_t t0 = st_cur;
        st_cur = st_nx1;
        st_nx1 = st_nx2;
        st_nx2 = t0;
    }

    // ---- epilogue ----
    const float* bt = bias + task * DD;
    const int er = lane >> 2;
    const int ec = (lane & 3) * 2;

    float scale = 1.0f;
    if (MODE == 1 && inte != nullptr) {
        const float* it = inte + task * EE;
        scale = it[0] + it[1] + it[2] + it[3];
    }

    uint32_t* Y32 = reinterpret_cast<uint32_t*>(Yo);
    #pragma unroll
    for (int mf = 0; mf < 4; ++mf) {
        const int m = m0 + wm * 64 + mf * 16 + er;
        #pragma unroll
        for (int nf = 0; nf < 4; ++nf) {
            const int n = n0 + wn * 32 + nf * 8 + ec;
            float2 b2 = *reinterpret_cast<const float2*>(bt + n);
            float v0 = fmaxf(acc[mf][nf][0] + b2.x, 0.0f) * scale;
            float v1 = fmaxf(acc[mf][nf][1] + b2.y, 0.0f) * scale;
            float v2 = fmaxf(acc[mf][nf][2] + b2.x, 0.0f) * scale;
            float v3 = fmaxf(acc[mf][nf][3] + b2.y, 0.0f) * scale;
            size_t o0, o1;
            if constexpr (MODE == 0) {          // [T][B][D]
                o0 = (((size_t)(task * BB + m)     * DD) + n) >> 1;
                o1 = (((size_t)(task * BB + m + 8) * DD) + n) >> 1;
            } else {                            // [B][T][D]
                o0 = (((size_t)m       * TT + task) * DD + n) >> 1;
                o1 = (((size_t)(m + 8) * TT + task) * DD + n) >> 1;
            }
            Y32[o0] = pack_h2(v0, v1);
            Y32[o1] = pack_h2(v2, v3);
        }
    }
}

// ============================================================================
// Gate + combine: 2 batch rows per block, 256 threads. teo: fp16 [B][T][D].
// Output: fp32 [B][T][D] (outf) OR fp16 [T][B][D] (outh).
// ============================================================================
__global__ __launch_bounds__(256)
void gate_combine(const fp16* __restrict__ teo, const float* __restrict__ Wg,
                  const float* __restrict__ bg, float* __restrict__ outf,
                  fp16* __restrict__ outh)
{
    __shared__ float s_teo[2][TT][DD];   // 32 KB
    __shared__ float s_g[2][TT][TT];

    const int tid  = threadIdx.x;
    const int half = tid >> 7;            // 0 or 1 -> batch row
    const int htid = tid & 127;
    const int warp = htid >> 5;           // 0..3 (task row within half)
    const int lane = tid & 31;

    const int b = blockIdx.x * 2 + half;
    const size_t base = (size_t)b * TT * DD;
    const uint32_t* t16 = reinterpret_cast<const uint32_t*>(teo) + (base >> 1);
    for (int idx = htid; idx < TT * DD / 2; idx += 128) {
        __half2 h = *reinterpret_cast<const __half2*>(t16 + idx);
        float2 f = __half22float2(h);
        s_teo[half][0][idx * 2]     = f.x;
        s_teo[half][0][idx * 2 + 1] = f.y;
    }
    __syncthreads();

    float a0 = 0.f, a1 = 0.f, a2 = 0.f, a3 = 0.f;
    for (int d = lane; d < DD; d += 32) {
        float v = s_teo[half][warp][d];
        float4 w = reinterpret_cast<const float4*>(Wg)[d];
        a0 = fmaf(v, w.x, a0);
        a1 = fmaf(v, w.y, a1);
        a2 = fmaf(v, w.z, a2);
        a3 = fmaf(v, w.w, a3);
    }
    #pragma unroll
    for (int off = 16; off; off >>= 1) {
        a0 += __shfl_xor_sync(0xffffffffu, a0, off);
        a1 += __shfl_xor_sync(0xffffffffu, a1, off);
        a2 += __shfl_xor_sync(0xffffffffu, a2, off);
        a3 += __shfl_xor_sync(0xffffffffu, a3, off);
    }
    if (lane == 0) {
        float l0 = a0 + bg[0], l1 = a1 + bg[1], l2 = a2 + bg[2], l3 = a3 + bg[3];
        float m = fmaxf(fmaxf(l0, l1), fmaxf(l2, l3));
        float e0 = __expf(l0 - m), e1 = __expf(l1 - m);
        float e2 = __expf(l2 - m), e3 = __expf(l3 - m);
        float inv = 1.0f / (e0 + e1 + e2 + e3);
        s_g[half][warp][0] = e0 * inv;
        s_g[half][warp][1] = e1 * inv;
        s_g[half][warp][2] = e2 * inv;
        s_g[half][warp][3] = e3 * inv;
    }
    __syncthreads();

    #pragma unroll
    for (int t = 0; t < TT; t++) {
        const float g0 = s_g[half][t][0], g1 = s_g[half][t][1];
        const float g2 = s_g[half][t][2], g3 = s_g[half][t][3];
        for (int d2 = htid; d2 < DD / 2; d2 += 128) {
            const int d = d2 * 2;
            float r0 = s_teo[half][t][d], r1 = s_teo[half][t][d + 1];
            r0 = fmaf(g0, s_teo[half][0][d], r0);  r1 = fmaf(g0, s_teo[half][0][d+1], r1);
            r0 = fmaf(g1, s_teo[half][1][d], r0);  r1 = fmaf(g1, s_teo[half][1][d+1], r1);
            r0 = fmaf(g2, s_teo[half][2][d], r0);  r1 = fmaf(g2, s_teo[half][2][d+1], r1);
            r0 = fmaf(g3, s_teo[half][3][d], r0);  r1 = fmaf(g3, s_teo[half][3][d+1], r1);
            if (outf != nullptr) {
                float2 v; v.x = r0; v.y = r1;
                *reinterpret_cast<float2*>(outf + base + (size_t)t * DD + d) = v;
            } else {
                size_t o = (((size_t)(t * BB + b) * DD) + d) >> 1;
                reinterpret_cast<uint32_t*>(outh)[o] = pack_h2(r0, r1);
            }
        }
    }
}

// ============================================================================
// launch
// ============================================================================
extern "C" void kernel_launch(void* const* d_in, const int* in_sizes, int n_in,
                              void* d_out, int out_size)
{
    const float* x    = (const float*)d_in[0];
    const float* W1   = (const float*)d_in[1];
    const float* b1   = (const float*)d_in[2];
    const float* W2   = (const float*)d_in[3];
    const float* b2   = (const float*)d_in[4];
    const float* inte = (const float*)d_in[5];
    const float* Wg   = (const float*)d_in[6];
    const float* bg   = (const float*)d_in[7];
    float* out = (float*)d_out;

    cudaFuncSetAttribute(gemm_pre<0>, cudaFuncAttributeMaxDynamicSharedMemorySize,
                         SMEM_TOTAL);
    cudaFuncSetAttribute(gemm_pre<1>, cudaFuncAttributeMaxDynamicSharedMemorySize,
                         SMEM_TOTAL);

    fp16 *ain, *t1, *w1, *w2, *teo;
    cudaGetSymbolAddress((void**)&ain, g_in);
    cudaGetSymbolAddress((void**)&t1,  g_t1);
    cudaGetSymbolAddress((void**)&w1,  g_w1);
    cudaGetSymbolAddress((void**)&w2,  g_w2);
    cudaGetSymbolAddress((void**)&teo, g_teo);

    // one merged prep launch: all weights + input activations
    prep_all<<<WBLK + ABLK, 256>>>(x, W1, W2, ain, w1, w2);

    dim3 ggrid(DD / BN, BB / BM, TT);             // (8, 32, 4) = 1024 CTAs

    for (int l = 0; l < LL; l++) {
        const fp16*  w1l = w1 + (size_t)l * TT * DD * DD;
        const fp16*  w2l = w2 + (size_t)l * TT * DD * DD;
        const float* b1l = b1 + (size_t)l * TT * DD;
        const float* b2l = b2 + (size_t)l * TT * DD;
        const float* il  = inte + (size_t)l * TT * EE;
        const float* Wgl = Wg + (size_t)l * DD * TT;
        const float* bgl = bg + (size_t)l * TT;

        gemm_pre<0><<<ggrid, 256, SMEM_TOTAL>>>(ain, w1l, b1l, nullptr, t1);
        gemm_pre<1><<<ggrid, 256, SMEM_TOTAL>>>(t1, w2l, b2l, il, teo);

        if (l == LL - 1)
            gate_combine<<<BB / 2, 256>>>(teo, Wgl, bgl, out, nullptr);
        else
            gate_combine<<<BB / 2, 256>>>(teo, Wgl, bgl, nullptr, ain);
    }
}

// round 15
// speedup vs baseline: 1.2379x; 1.0125x over previous
#include <cuda_runtime.h>
#include <cuda_fp16.h>
#include <cstdint>

// Problem constants: B=4096 batch, T=4 tasks, D=1024 dim, L=2 layers, E=4.
#define BB 4096
#define TT 4
#define DD 1024
#define LL 2
#define EE 4

// GEMM tiling: 256 threads, 8 warps (2m x 4n), per-warp 64x32. 2 CTAs/SM.
#define BM 128
#define BN 128
#define KC 64
#define NCHUNK (DD / KC)   // 16
#define NSTAGE 3

// SMEM stage: A [128r][128B] = 16KB, W [128r][128B] = 16KB
#define OFF_A 0
#define OFF_W 16384
#define STAGE 32768
#define SMEM_TOTAL (NSTAGE * STAGE)   // 98304 -> two CTAs fit in 228KB

#define SW128(x) ((x) ^ (((x) >> 3) & 0x70))

typedef __half fp16;

// -------- scratch (allocation-free: __device__ globals) --------
__device__ fp16  g_in [TT * BB * DD];        // act in  [T][B][D]
__device__ fp16  g_t1 [TT * BB * DD];        // stage-1 [T][B][D]
__device__ fp16  g_w1 [LL * TT * DD * DD];   // W1' [L][T][n][k]
__device__ fp16  g_w2 [LL * TT * DD * DD];   // W2' [L][T][n][k]
__device__ fp16  g_teo[BB * TT * DD];        // fp16 [B][T][D]

// ---------------------------------------------------------------------------
__device__ __forceinline__ uint32_t smem_u32(const void* p) {
    uint32_t a;
    asm("{ .reg .u64 t; cvta.to.shared.u64 t, %1; cvt.u32.u64 %0, t; }"
        : "=r"(a) : "l"(p));
    return a;
}

__device__ __forceinline__ void ldsm_x4(uint32_t& r0, uint32_t& r1,
                                        uint32_t& r2, uint32_t& r3,
                                        uint32_t addr) {
    asm volatile("ldmatrix.sync.aligned.m8n8.x4.shared.b16 {%0,%1,%2,%3}, [%4];"
                 : "=r"(r0), "=r"(r1), "=r"(r2), "=r"(r3) : "r"(addr));
}

__device__ __forceinline__ void mma_fp16(float* c, const uint32_t* a,
                                         const uint32_t* b) {
    asm volatile(
        "mma.sync.aligned.m16n8k16.row.col.f32.f16.f16.f32 "
        "{%0,%1,%2,%3}, {%4,%5,%6,%7}, {%8,%9}, {%0,%1,%2,%3};"
        : "+f"(c[0]), "+f"(c[1]), "+f"(c[2]), "+f"(c[3])
        : "r"(a[0]), "r"(a[1]), "r"(a[2]), "r"(a[3]), "r"(b[0]), "r"(b[1]));
}

#define CPA16(dst, src) \
    asm volatile("cp.async.cg.shared.global [%0], [%1], 16;" :: "r"(dst), "l"(src))
#define CPCOMMIT() asm volatile("cp.async.commit_group;" ::: "memory")
#define CPWAIT1()  asm volatile("cp.async.wait_group 1;"  ::: "memory")

__device__ __forceinline__ uint32_t pack_h2(float v0, float v1) {
    __half2 h = __floats2half2_rn(v0, v1);
    return *reinterpret_cast<uint32_t*>(&h);
}

// ============================================================================
// prep (merged): blocks [0, WBLK) convert+transpose weights; blocks
// [WBLK, WBLK+ABLK) convert activations. All blocks 256 threads.
// ============================================================================
#define WBLK (32 * 32 * LL * TT * 2)          // 16384 weight-tile blocks
#define ABLK ((BB * TT * DD / 2) / 256)       // 32768 activation blocks

__global__ __launch_bounds__(256)
void prep_all(const float* __restrict__ x,
              const float* __restrict__ W1, const float* __restrict__ W2,
              fp16* __restrict__ xa,
              fp16* __restrict__ o1, fp16* __restrict__ o2)
{
    const int bid = blockIdx.x;
    if (bid < WBLK) {
        __shared__ float tile[32][33];
        const int z  = bid >> 10;            // 0..15
        const int ky = (bid >> 5) & 31;
        const int nx = bid & 31;
        const int t    = z & (TT - 1);
        const int wsel = (z >> 2) & 1;
        const int l    = z >> 3;
        const size_t woff = ((size_t)l * TT + t) * DD * DD;
        const float* Wt = (wsel ? W2 : W1) + woff;
        uint16_t* ot = reinterpret_cast<uint16_t*>(wsel ? o2 : o1) + woff;

        const int k0 = ky * 32, n0 = nx * 32;
        const int tx = threadIdx.x & 31, ty = threadIdx.x >> 5;   // 32 x 8
        #pragma unroll
        for (int i = 0; i < 4; i++)
            tile[ty + i * 8][tx] = Wt[(size_t)(k0 + ty + i * 8) * DD + n0 + tx];
        __syncthreads();
        #pragma unroll
        for (int i = 0; i < 4; i++) {
            int n = n0 + ty + i * 8;
            __half h = __float2half_rn(tile[tx][ty + i * 8]);
            ot[(size_t)n * DD + k0 + tx] = *reinterpret_cast<uint16_t*>(&h);
        }
    } else {
        int p = (bid - WBLK) * 256 + threadIdx.x;   // pair index
        int d2 = p & (DD / 2 - 1);
        int bt = p >> 9;                            // DD/2 = 512
        int t = bt & (TT - 1);
        int b = bt >> 2;
        float2 v = reinterpret_cast<const float2*>(x)[p];
        size_t o = (((size_t)(t * BB + b) * DD) >> 1) + d2;
        reinterpret_cast<uint32_t*>(xa)[o] = pack_h2(v.x, v.y);
    }
}

// ============================================================================
// fp16 mma.sync GEMM:  acc = A @ W   (per-warp 64x32 tile, 2 CTAs/SM)
// Mainloop = round-12 structure (measured best); stage bases rotate in regs.
// MODE 0: Y = relu(acc + b)            -> fp16 [T][B][D]
// MODE 1: Y = relu(acc + b) * scale    -> fp16 [B][T][D]
// ============================================================================
template <int MODE>
__global__ __launch_bounds__(256, 2)
void gemm_pre(const fp16* __restrict__ Ain, const fp16* __restrict__ Wm,
              const float* __restrict__ bias, const float* __restrict__ inte,
              fp16* __restrict__ Yo)
{
    extern __shared__ char smem[];
    const uint32_t sbase = smem_u32(smem);
    const int tid  = threadIdx.x;
    const int warp = tid >> 5;
    const int lane = tid & 31;
    const int task = blockIdx.z;
    const int m0   = blockIdx.y * BM;
    const int n0   = blockIdx.x * BN;

    const fp16* ab = Ain + (size_t)(task * BB + m0) * DD;
    const fp16* wb = Wm  + (size_t)(task * DD + n0) * DD;

    const int lrow = tid >> 3;          // 0..31 (per it: +32)
    const int k16  = tid & 7;           // 16B seg within 128B row

    auto issue = [&](int k0, uint32_t stb) {
        #pragma unroll
        for (int it = 0; it < 4; it++) {
            const int row = it * 32 + lrow;
            const uint32_t dsw = SW128((uint32_t)(row * 128 + k16 * 16));
            const size_t so = (size_t)row * DD + k0 + k16 * 8;
            CPA16(stb + OFF_A + dsw, ab + so);
            CPA16(stb + OFF_W + dsw, wb + so);
        }
    };

    uint32_t st_cur = sbase;
    uint32_t st_nx1 = sbase + STAGE;
    uint32_t st_nx2 = sbase + 2 * STAGE;

    issue(0, st_cur); CPCOMMIT();
    issue(KC, st_nx1); CPCOMMIT();

    float acc[4][4][4];
    #pragma unroll
    for (int i = 0; i < 4; ++i)
        #pragma unroll
        for (int j = 0; j < 4; ++j)
            #pragma unroll
            for (int r = 0; r < 4; ++r) acc[i][j][r] = 0.0f;

    const int wm = warp & 1;    // 64-row group
    const int wn = warp >> 1;   // 32-col group
    const int a_lrow = lane & 15;
    const int a_lcol = (lane >> 4) << 4;
    const int b_row  = ((lane >> 4) & 1) * 8 + (lane & 7);
    const int b_boff = ((lane >> 3) & 1) * 16;

    for (int c = 0; c < NCHUNK; ++c) {
        CPWAIT1();
        __syncthreads();
        // prefetch stage c+2 (its buffer was last read in chunk c-1; every
        // warp passed this barrier, so all c-1 reads are complete)
        if (c + 2 < NCHUNK) issue((c + 2) * KC, st_nx2);
        CPCOMMIT();

        const uint32_t stb = st_cur;

        #pragma unroll
        for (int ks = 0; ks < 4; ++ks) {
            uint32_t ah[4][4], bh[4][2];
            #pragma unroll
            for (int mf = 0; mf < 4; ++mf) {
                uint32_t off = SW128((uint32_t)(
                    (wm * 64 + mf * 16 + a_lrow) * 128 + ks * 32 + a_lcol));
                ldsm_x4(ah[mf][0], ah[mf][1], ah[mf][2], ah[mf][3],
                        stb + OFF_A + off);
            }
            #pragma unroll
            for (int nfp = 0; nfp < 2; ++nfp) {
                uint32_t off = SW128((uint32_t)(
                    (wn * 32 + nfp * 16 + b_row) * 128 + ks * 32 + b_boff));
                ldsm_x4(bh[2*nfp][0], bh[2*nfp][1], bh[2*nfp+1][0], bh[2*nfp+1][1],
                        stb + OFF_W + off);
            }
            #pragma unroll
            for (int mf = 0; mf < 4; ++mf)
                #pragma unroll
                for (int nf = 0; nf < 4; ++nf)
                    mma_fp16(acc[mf][nf], ah[mf], bh[nf]);
        }

        uint32_t t0 = st_cur;
        st_cur = st_nx1;
        st_nx1 = st_nx2;
        st_nx2 = t0;
    }

    // ---- epilogue ----
    const float* bt = bias + task * DD;
    const int er = lane >> 2;
    const int ec = (lane & 3) * 2;

    float scale = 1.0f;
    if (MODE == 1 && inte != nullptr) {
        const float* it = inte + task * EE;
        scale = it[0] + it[1] + it[2] + it[3];
    }

    uint32_t* Y32 = reinterpret_cast<uint32_t*>(Yo);
    #pragma unroll
    for (int mf = 0; mf < 4; ++mf) {
        const int m = m0 + wm * 64 + mf * 16 + er;
        #pragma unroll
        for (int nf = 0; nf < 4; ++nf) {
            const int n = n0 + wn * 32 + nf * 8 + ec;
            float2 b2 = *reinterpret_cast<const float2*>(bt + n);
            float v0 = fmaxf(acc[mf][nf][0] + b2.x, 0.0f) * scale;
            float v1 = fmaxf(acc[mf][nf][1] + b2.y, 0.0f) * scale;
            float v2 = fmaxf(acc[mf][nf][2] + b2.x, 0.0f) * scale;
            float v3 = fmaxf(acc[mf][nf][3] + b2.y, 0.0f) * scale;
            size_t o0, o1;
            if constexpr (MODE == 0) {          // [T][B][D]
                o0 = (((size_t)(task * BB + m)     * DD) + n) >> 1;
                o1 = (((size_t)(task * BB + m + 8) * DD) + n) >> 1;
            } else {                            // [B][T][D]
                o0 = (((size_t)m       * TT + task) * DD + n) >> 1;
                o1 = (((size_t)(m + 8) * TT + task) * DD + n) >> 1;
            }
            Y32[o0] = pack_h2(v0, v1);
            Y32[o1] = pack_h2(v2, v3);
        }
    }
}

// ============================================================================
// Gate + combine: 2 batch rows per block, 256 threads. teo: fp16 [B][T][D].
// Combine phase restructured: per d-pair, load 4 task values once, compute
// all 4 outputs in registers (8 LDS + 32 FMA + 4 ST per pair vs 40 LDS).
// Output: fp32 [B][T][D] (outf) OR fp16 [T][B][D] (outh).
// ============================================================================
__global__ __launch_bounds__(256)
void gate_combine(const fp16* __restrict__ teo, const float* __restrict__ Wg,
                  const float* __restrict__ bg, float* __restrict__ outf,
                  fp16* __restrict__ outh)
{
    __shared__ float s_teo[2][TT][DD];   // 32 KB
    __shared__ float s_g[2][TT][TT];

    const int tid  = threadIdx.x;
    const int half = tid >> 7;            // 0 or 1 -> batch row
    const int htid = tid & 127;
    const int warp = htid >> 5;           // 0..3 (task row within half)
    const int lane = tid & 31;

    const int b = blockIdx.x * 2 + half;
    const size_t base = (size_t)b * TT * DD;
    const uint32_t* t16 = reinterpret_cast<const uint32_t*>(teo) + (base >> 1);
    for (int idx = htid; idx < TT * DD / 2; idx += 128) {
        __half2 h = *reinterpret_cast<const __half2*>(t16 + idx);
        float2 f = __half22float2(h);
        s_teo[half][0][idx * 2]     = f.x;
        s_teo[half][0][idx * 2 + 1] = f.y;
    }
    __syncthreads();

    float a0 = 0.f, a1 = 0.f, a2 = 0.f, a3 = 0.f;
    for (int d = lane; d < DD; d += 32) {
        float v = s_teo[half][warp][d];
        float4 w = reinterpret_cast<const float4*>(Wg)[d];
        a0 = fmaf(v, w.x, a0);
        a1 = fmaf(v, w.y, a1);
        a2 = fmaf(v, w.z, a2);
        a3 = fmaf(v, w.w, a3);
    }
    #pragma unroll
    for (int off = 16; off; off >>= 1) {
        a0 += __shfl_xor_sync(0xffffffffu, a0, off);
        a1 += __shfl_xor_sync(0xffffffffu, a1, off);
        a2 += __shfl_xor_sync(0xffffffffu, a2, off);
        a3 += __shfl_xor_sync(0xffffffffu, a3, off);
    }
    if (lane == 0) {
        float l0 = a0 + bg[0], l1 = a1 + bg[1], l2 = a2 + bg[2], l3 = a3 + bg[3];
        float m = fmaxf(fmaxf(l0, l1), fmaxf(l2, l3));
        float e0 = __expf(l0 - m), e1 = __expf(l1 - m);
        float e2 = __expf(l2 - m), e3 = __expf(l3 - m);
        float inv = 1.0f / (e0 + e1 + e2 + e3);
        s_g[half][warp][0] = e0 * inv;
        s_g[half][warp][1] = e1 * inv;
        s_g[half][warp][2] = e2 * inv;
        s_g[half][warp][3] = e3 * inv;
    }
    __syncthreads();

    // gate matrix into registers (16 values, one-time)
    float gm[TT][TT];
    #pragma unroll
    for (int t = 0; t < TT; t++)
        #pragma unroll
        for (int k = 0; k < TT; k++)
            gm[t][k] = s_g[half][t][k];

    // combine: per d-pair, read 4 task values once, produce 4 outputs
    for (int d2 = htid; d2 < DD / 2; d2 += 128) {
        const int d = d2 * 2;
        float2 v[TT];
        #pragma unroll
        for (int k = 0; k < TT; k++)
            v[k] = *reinterpret_cast<const float2*>(&s_teo[half][k][d]);

        #pragma unroll
        for (int t = 0; t < TT; t++) {
            float r0 = v[t].x, r1 = v[t].y;
            #pragma unroll
            for (int k = 0; k < TT; k++) {
                r0 = fmaf(gm[t][k], v[k].x, r0);
                r1 = fmaf(gm[t][k], v[k].y, r1);
            }
            if (outf != nullptr) {
                float2 o; o.x = r0; o.y = r1;
                *reinterpret_cast<float2*>(outf + base + (size_t)t * DD + d) = o;
            } else {
                size_t o = (((size_t)(t * BB + b) * DD) + d) >> 1;
                reinterpret_cast<uint32_t*>(outh)[o] = pack_h2(r0, r1);
            }
        }
    }
}

// ============================================================================
// launch
// ============================================================================
extern "C" void kernel_launch(void* const* d_in, const int* in_sizes, int n_in,
                              void* d_out, int out_size)
{
    const float* x    = (const float*)d_in[0];
    const float* W1   = (const float*)d_in[1];
    const float* b1   = (const float*)d_in[2];
    const float* W2   = (const float*)d_in[3];
    const float* b2   = (const float*)d_in[4];
    const float* inte = (const float*)d_in[5];
    const float* Wg   = (const float*)d_in[6];
    const float* bg   = (const float*)d_in[7];
    float* out = (float*)d_out;

    cudaFuncSetAttribute(gemm_pre<0>, cudaFuncAttributeMaxDynamicSharedMemorySize,
                         SMEM_TOTAL);
    cudaFuncSetAttribute(gemm_pre<1>, cudaFuncAttributeMaxDynamicSharedMemorySize,
                         SMEM_TOTAL);

    fp16 *ain, *t1, *w1, *w2, *teo;
    cudaGetSymbolAddress((void**)&ain, g_in);
    cudaGetSymbolAddress((void**)&t1,  g_t1);
    cudaGetSymbolAddress((void**)&w1,  g_w1);
    cudaGetSymbolAddress((void**)&w2,  g_w2);
    cudaGetSymbolAddress((void**)&teo, g_teo);

    // one merged prep launch: all weights + input activations
    prep_all<<<WBLK + ABLK, 256>>>(x, W1, W2, ain, w1, w2);

    dim3 ggrid(DD / BN, BB / BM, TT);             // (8, 32, 4) = 1024 CTAs

    for (int l = 0; l < LL; l++) {
        const fp16*  w1l = w1 + (size_t)l * TT * DD * DD;
        const fp16*  w2l = w2 + (size_t)l * TT * DD * DD;
        const float* b1l = b1 + (size_t)l * TT * DD;
        const float* b2l = b2 + (size_t)l * TT * DD;
        const float* il  = inte + (size_t)l * TT * EE;
        const float* Wgl = Wg + (size_t)l * DD * TT;
        const float* bgl = bg + (size_t)l * TT;

        gemm_pre<0><<<ggrid, 256, SMEM_TOTAL>>>(ain, w1l, b1l, nullptr, t1);
        gemm_pre<1><<<ggrid, 256, SMEM_TOTAL>>>(t1, w2l, b2l, il, teo);

        if (l == LL - 1)
            gate_combine<<<BB / 2, 256>>>(teo, Wgl, bgl, out, nullptr);
        else
            gate_combine<<<BB / 2, 256>>>(teo, Wgl, bgl, nullptr, ain);
    }
}

// round 16
// speedup vs baseline: 1.2588x; 1.0169x over previous
#include <cuda_runtime.h>
#include <cuda_fp16.h>
#include <cstdint>

// Problem constants: B=4096 batch, T=4 tasks, D=1024 dim, L=2 layers, E=4.
#define BB 4096
#define TT 4
#define DD 1024
#define LL 2
#define EE 4

// GEMM tiling: 256 threads, 8 warps (2m x 4n), per-warp 64x32. 2 CTAs/SM.
// Persistent grid-stride: 304 CTAs loop over all 1024 tiles.
#define BM 128
#define BN 128
#define KC 64
#define NCHUNK (DD / KC)   // 16
#define NSTAGE 3
#define NTILES ((DD / BN) * (BB / BM) * TT)   // 1024
#define PERS   304                             // 152 SMs x 2 CTAs

// SMEM stage: A [128r][128B] = 16KB, W [128r][128B] = 16KB
#define OFF_A 0
#define OFF_W 16384
#define STAGE 32768
#define SMEM_TOTAL (NSTAGE * STAGE)   // 98304 -> two CTAs fit in 228KB

#define SW128(x) ((x) ^ (((x) >> 3) & 0x70))

typedef __half fp16;

// -------- scratch (allocation-free: __device__ globals) --------
__device__ fp16  g_in [TT * BB * DD];        // act in  [T][B][D]
__device__ fp16  g_t1 [TT * BB * DD];        // stage-1 [T][B][D]
__device__ fp16  g_w1 [LL * TT * DD * DD];   // W1' [L][T][n][k]
__device__ fp16  g_w2 [LL * TT * DD * DD];   // W2' [L][T][n][k]
__device__ fp16  g_teo[BB * TT * DD];        // fp16 [B][T][D]

// ---------------------------------------------------------------------------
__device__ __forceinline__ uint32_t smem_u32(const void* p) {
    uint32_t a;
    asm("{ .reg .u64 t; cvta.to.shared.u64 t, %1; cvt.u32.u64 %0, t; }"
        : "=r"(a) : "l"(p));
    return a;
}

__device__ __forceinline__ void ldsm_x4(uint32_t& r0, uint32_t& r1,
                                        uint32_t& r2, uint32_t& r3,
                                        uint32_t addr) {
    asm volatile("ldmatrix.sync.aligned.m8n8.x4.shared.b16 {%0,%1,%2,%3}, [%4];"
                 : "=r"(r0), "=r"(r1), "=r"(r2), "=r"(r3) : "r"(addr));
}

__device__ __forceinline__ void mma_fp16(float* c, const uint32_t* a,
                                         const uint32_t* b) {
    asm volatile(
        "mma.sync.aligned.m16n8k16.row.col.f32.f16.f16.f32 "
        "{%0,%1,%2,%3}, {%4,%5,%6,%7}, {%8,%9}, {%0,%1,%2,%3};"
        : "+f"(c[0]), "+f"(c[1]), "+f"(c[2]), "+f"(c[3])
        : "r"(a[0]), "r"(a[1]), "r"(a[2]), "r"(a[3]), "r"(b[0]), "r"(b[1]));
}

#define CPA16(dst, src) \
    asm volatile("cp.async.cg.shared.global [%0], [%1], 16;" :: "r"(dst), "l"(src))
#define CPCOMMIT() asm volatile("cp.async.commit_group;" ::: "memory")
#define CPWAIT1()  asm volatile("cp.async.wait_group 1;"  ::: "memory")

__device__ __forceinline__ uint32_t pack_h2(float v0, float v1) {
    __half2 h = __floats2half2_rn(v0, v1);
    return *reinterpret_cast<uint32_t*>(&h);
}

// ============================================================================
// prep (merged): blocks [0, WBLK) convert+transpose weights; blocks
// [WBLK, WBLK+ABLK) convert activations. All blocks 256 threads.
// ============================================================================
#define WBLK (32 * 32 * LL * TT * 2)          // 16384 weight-tile blocks
#define ABLK ((BB * TT * DD / 2) / 256)       // 32768 activation blocks

__global__ __launch_bounds__(256)
void prep_all(const float* __restrict__ x,
              const float* __restrict__ W1, const float* __restrict__ W2,
              fp16* __restrict__ xa,
              fp16* __restrict__ o1, fp16* __restrict__ o2)
{
    const int bid = blockIdx.x;
    if (bid < WBLK) {
        __shared__ float tile[32][33];
        const int z  = bid >> 10;            // 0..15
        const int ky = (bid >> 5) & 31;
        const int nx = bid & 31;
        const int t    = z & (TT - 1);
        const int wsel = (z >> 2) & 1;
        const int l    = z >> 3;
        const size_t woff = ((size_t)l * TT + t) * DD * DD;
        const float* Wt = (wsel ? W2 : W1) + woff;
        uint16_t* ot = reinterpret_cast<uint16_t*>(wsel ? o2 : o1) + woff;

        const int k0 = ky * 32, n0 = nx * 32;
        const int tx = threadIdx.x & 31, ty = threadIdx.x >> 5;   // 32 x 8
        #pragma unroll
        for (int i = 0; i < 4; i++)
            tile[ty + i * 8][tx] = Wt[(size_t)(k0 + ty + i * 8) * DD + n0 + tx];
        __syncthreads();
        #pragma unroll
        for (int i = 0; i < 4; i++) {
            int n = n0 + ty + i * 8;
            __half h = __float2half_rn(tile[tx][ty + i * 8]);
            ot[(size_t)n * DD + k0 + tx] = *reinterpret_cast<uint16_t*>(&h);
        }
    } else {
        int p = (bid - WBLK) * 256 + threadIdx.x;   // pair index
        int d2 = p & (DD / 2 - 1);
        int bt = p >> 9;                            // DD/2 = 512
        int t = bt & (TT - 1);
        int b = bt >> 2;
        float2 v = reinterpret_cast<const float2*>(x)[p];
        size_t o = (((size_t)(t * BB + b) * DD) >> 1) + d2;
        reinterpret_cast<uint32_t*>(xa)[o] = pack_h2(v.x, v.y);
    }
}

// ============================================================================
// fp16 mma.sync GEMM, persistent grid-stride over tiles.
// Inner structure per tile = round-12 (measured best).
// MODE 0: Y = relu(acc + b)            -> fp16 [T][B][D]
// MODE 1: Y = relu(acc + b) * scale    -> fp16 [B][T][D]
// ============================================================================
template <int MODE>
__global__ __launch_bounds__(256, 2)
void gemm_pre(const fp16* __restrict__ Ain, const fp16* __restrict__ Wm,
              const float* __restrict__ bias, const float* __restrict__ inte,
              fp16* __restrict__ Yo)
{
    extern __shared__ char smem[];
    const uint32_t sbase = smem_u32(smem);
    const int tid  = threadIdx.x;
    const int warp = tid >> 5;
    const int lane = tid & 31;

    const int lrow = tid >> 3;          // 0..31 (per it: +32)
    const int k16  = tid & 7;           // 16B seg within 128B row

    const int wm = warp & 1;    // 64-row group
    const int wn = warp >> 1;   // 32-col group
    const int a_lrow = lane & 15;
    const int a_lcol = (lane >> 4) << 4;
    const int b_row  = ((lane >> 4) & 1) * 8 + (lane & 7);
    const int b_boff = ((lane >> 3) & 1) * 16;
    const int er = lane >> 2;
    const int ec = (lane & 3) * 2;

    uint32_t* Y32 = reinterpret_cast<uint32_t*>(Yo);

    // rotating stage bases carry across tiles (buffers interchangeable)
    uint32_t st_cur = sbase;
    uint32_t st_nx1 = sbase + STAGE;
    uint32_t st_nx2 = sbase + 2 * STAGE;

    for (int tile = blockIdx.x; tile < NTILES; tile += PERS) {
        // decode tile -> (task, m0, n0); done ONCE per tile, outside hot loop
        const int task = tile >> 8;               // 256 tiles per task
        const int rem  = tile & 255;
        const int m0   = (rem >> 3) * BM;
        const int n0   = (rem & 7) * BN;

        const fp16* ab = Ain + (size_t)(task * BB + m0) * DD;
        const fp16* wb = Wm  + (size_t)(task * DD + n0) * DD;

        auto issue = [&](int k0, uint32_t stb) {
            #pragma unroll
            for (int it = 0; it < 4; it++) {
                const int row = it * 32 + lrow;
                const uint32_t dsw = SW128((uint32_t)(row * 128 + k16 * 16));
                const size_t so = (size_t)row * DD + k0 + k16 * 8;
                CPA16(stb + OFF_A + dsw, ab + so);
                CPA16(stb + OFF_W + dsw, wb + so);
            }
        };

        // protect stage buffers: other warps may still be reading the last
        // tile's chunks when this warp starts overwriting them.
        __syncthreads();

        issue(0, st_cur); CPCOMMIT();
        issue(KC, st_nx1); CPCOMMIT();

        float acc[4][4][4];
        #pragma unroll
        for (int i = 0; i < 4; ++i)
            #pragma unroll
            for (int j = 0; j < 4; ++j)
                #pragma unroll
                for (int r = 0; r < 4; ++r) acc[i][j][r] = 0.0f;

        #pragma unroll 1
        for (int c = 0; c < NCHUNK; ++c) {
            CPWAIT1();
            __syncthreads();
            // prefetch stage c+2 (buffer last read in chunk c-1; the barrier
            // above guarantees all warps finished those reads)
            if (c + 2 < NCHUNK) issue((c + 2) * KC, st_nx2);
            CPCOMMIT();

            const uint32_t stb = st_cur;

            #pragma unroll
            for (int ks = 0; ks < 4; ++ks) {
                uint32_t ah[4][4], bh[4][2];
                #pragma unroll
                for (int mf = 0; mf < 4; ++mf) {
                    uint32_t off = SW128((uint32_t)(
                        (wm * 64 + mf * 16 + a_lrow) * 128 + ks * 32 + a_lcol));
                    ldsm_x4(ah[mf][0], ah[mf][1], ah[mf][2], ah[mf][3],
                            stb + OFF_A + off);
                }
                #pragma unroll
                for (int nfp = 0; nfp < 2; ++nfp) {
                    uint32_t off = SW128((uint32_t)(
                        (wn * 32 + nfp * 16 + b_row) * 128 + ks * 32 + b_boff));
                    ldsm_x4(bh[2*nfp][0], bh[2*nfp][1],
                            bh[2*nfp+1][0], bh[2*nfp+1][1],
                            stb + OFF_W + off);
                }
                #pragma unroll
                for (int mf = 0; mf < 4; ++mf)
                    #pragma unroll
                    for (int nf = 0; nf < 4; ++nf)
                        mma_fp16(acc[mf][nf], ah[mf], bh[nf]);
            }

            uint32_t t0 = st_cur;
            st_cur = st_nx1;
            st_nx1 = st_nx2;
            st_nx2 = t0;
        }

        // ---- epilogue for this tile ----
        const float* bt = bias + task * DD;
        float scale = 1.0f;
        if (MODE == 1 && inte != nullptr) {
            const float* it = inte + task * EE;
            scale = it[0] + it[1] + it[2] + it[3];
        }

        #pragma unroll
        for (int mf = 0; mf < 4; ++mf) {
            const int m = m0 + wm * 64 + mf * 16 + er;
            #pragma unroll
            for (int nf = 0; nf < 4; ++nf) {
                const int n = n0 + wn * 32 + nf * 8 + ec;
                float2 b2 = *reinterpret_cast<const float2*>(bt + n);
                float v0 = fmaxf(acc[mf][nf][0] + b2.x, 0.0f) * scale;
                float v1 = fmaxf(acc[mf][nf][1] + b2.y, 0.0f) * scale;
                float v2 = fmaxf(acc[mf][nf][2] + b2.x, 0.0f) * scale;
                float v3 = fmaxf(acc[mf][nf][3] + b2.y, 0.0f) * scale;
                size_t o0, o1;
                if constexpr (MODE == 0) {          // [T][B][D]
                    o0 = (((size_t)(task * BB + m)     * DD) + n) >> 1;
                    o1 = (((size_t)(task * BB + m + 8) * DD) + n) >> 1;
                } else {                            // [B][T][D]
                    o0 = (((size_t)m       * TT + task) * DD + n) >> 1;
                    o1 = (((size_t)(m + 8) * TT + task) * DD + n) >> 1;
                }
                Y32[o0] = pack_h2(v0, v1);
                Y32[o1] = pack_h2(v2, v3);
            }
        }
    }
}

// ============================================================================
// Gate + combine: 2 batch rows per block, 256 threads. teo: fp16 [B][T][D].
// Output: fp32 [B][T][D] (outf) OR fp16 [T][B][D] (outh).
// ============================================================================
__global__ __launch_bounds__(256)
void gate_combine(const fp16* __restrict__ teo, const float* __restrict__ Wg,
                  const float* __restrict__ bg, float* __restrict__ outf,
                  fp16* __restrict__ outh)
{
    __shared__ float s_teo[2][TT][DD];   // 32 KB
    __shared__ float s_g[2][TT][TT];

    const int tid  = threadIdx.x;
    const int half = tid >> 7;            // 0 or 1 -> batch row
    const int htid = tid & 127;
    const int warp = htid >> 5;           // 0..3 (task row within half)
    const int lane = tid & 31;

    const int b = blockIdx.x * 2 + half;
    const size_t base = (size_t)b * TT * DD;
    const uint32_t* t16 = reinterpret_cast<const uint32_t*>(teo) + (base >> 1);
    for (int idx = htid; idx < TT * DD / 2; idx += 128) {
        __half2 h = *reinterpret_cast<const __half2*>(t16 + idx);
        float2 f = __half22float2(h);
        s_teo[half][0][idx * 2]     = f.x;
        s_teo[half][0][idx * 2 + 1] = f.y;
    }
    __syncthreads();

    float a0 = 0.f, a1 = 0.f, a2 = 0.f, a3 = 0.f;
    for (int d = lane; d < DD; d += 32) {
        float v = s_teo[half][warp][d];
        float4 w = reinterpret_cast<const float4*>(Wg)[d];
        a0 = fmaf(v, w.x, a0);
        a1 = fmaf(v, w.y, a1);
        a2 = fmaf(v, w.z, a2);
        a3 = fmaf(v, w.w, a3);
    }
    #pragma unroll
    for (int off = 16; off; off >>= 1) {
        a0 += __shfl_xor_sync(0xffffffffu, a0, off);
        a1 += __shfl_xor_sync(0xffffffffu, a1, off);
        a2 += __shfl_xor_sync(0xffffffffu, a2, off);
        a3 += __shfl_xor_sync(0xffffffffu, a3, off);
    }
    if (lane == 0) {
        float l0 = a0 + bg[0], l1 = a1 + bg[1], l2 = a2 + bg[2], l3 = a3 + bg[3];
        float m = fmaxf(fmaxf(l0, l1), fmaxf(l2, l3));
        float e0 = __expf(l0 - m), e1 = __expf(l1 - m);
        float e2 = __expf(l2 - m), e3 = __expf(l3 - m);
        float inv = 1.0f / (e0 + e1 + e2 + e3);
        s_g[half][warp][0] = e0 * inv;
        s_g[half][warp][1] = e1 * inv;
        s_g[half][warp][2] = e2 * inv;
        s_g[half][warp][3] = e3 * inv;
    }
    __syncthreads();

    float gm[TT][TT];
    #pragma unroll
    for (int t = 0; t < TT; t++)
        #pragma unroll
        for (int k = 0; k < TT; k++)
            gm[t][k] = s_g[half][t][k];

    for (int d2 = htid; d2 < DD / 2; d2 += 128) {
        const int d = d2 * 2;
        float2 v[TT];
        #pragma unroll
        for (int k = 0; k < TT; k++)
            v[k] = *reinterpret_cast<const float2*>(&s_teo[half][k][d]);

        #pragma unroll
        for (int t = 0; t < TT; t++) {
            float r0 = v[t].x, r1 = v[t].y;
            #pragma unroll
            for (int k = 0; k < TT; k++) {
                r0 = fmaf(gm[t][k], v[k].x, r0);
                r1 = fmaf(gm[t][k], v[k].y, r1);
            }
            if (outf != nullptr) {
                float2 o; o.x = r0; o.y = r1;
                *reinterpret_cast<float2*>(outf + base + (size_t)t * DD + d) = o;
            } else {
                size_t o = (((size_t)(t * BB + b) * DD) + d) >> 1;
                reinterpret_cast<uint32_t*>(outh)[o] = pack_h2(r0, r1);
            }
        }
    }
}

// ============================================================================
// launch
// ============================================================================
extern "C" void kernel_launch(void* const* d_in, const int* in_sizes, int n_in,
                              void* d_out, int out_size)
{
    const float* x    = (const float*)d_in[0];
    const float* W1   = (const float*)d_in[1];
    const float* b1   = (const float*)d_in[2];
    const float* W2   = (const float*)d_in[3];
    const float* b2   = (const float*)d_in[4];
    const float* inte = (const float*)d_in[5];
    const float* Wg   = (const float*)d_in[6];
    const float* bg   = (const float*)d_in[7];
    float* out = (float*)d_out;

    cudaFuncSetAttribute(gemm_pre<0>, cudaFuncAttributeMaxDynamicSharedMemorySize,
                         SMEM_TOTAL);
    cudaFuncSetAttribute(gemm_pre<1>, cudaFuncAttributeMaxDynamicSharedMemorySize,
                         SMEM_TOTAL);

    fp16 *ain, *t1, *w1, *w2, *teo;
    cudaGetSymbolAddress((void**)&ain, g_in);
    cudaGetSymbolAddress((void**)&t1,  g_t1);
    cudaGetSymbolAddress((void**)&w1,  g_w1);
    cudaGetSymbolAddress((void**)&w2,  g_w2);
    cudaGetSymbolAddress((void**)&teo, g_teo);

    // one merged prep launch: all weights + input activations
    prep_all<<<WBLK + ABLK, 256>>>(x, W1, W2, ain, w1, w2);

    for (int l = 0; l < LL; l++) {
        const fp16*  w1l = w1 + (size_t)l * TT * DD * DD;
        const fp16*  w2l = w2 + (size_t)l * TT * DD * DD;
        const float* b1l = b1 + (size_t)l * TT * DD;
        const float* b2l = b2 + (size_t)l * TT * DD;
        const float* il  = inte + (size_t)l * TT * EE;
        const float* Wgl = Wg + (size_t)l * DD * TT;
        const float* bgl = bg + (size_t)l * TT;

        gemm_pre<0><<<PERS, 256, SMEM_TOTAL>>>(ain, w1l, b1l, nullptr, t1);
        gemm_pre<1><<<PERS, 256, SMEM_TOTAL>>>(t1, w2l, b2l, il, teo);

        if (l == LL - 1)
            gate_combine<<<BB / 2, 256>>>(teo, Wgl, bgl, out, nullptr);
        else
            gate_combine<<<BB / 2, 256>>>(teo, Wgl, bgl, nullptr, ain);
    }
}

// round 17
// speedup vs baseline: 1.2892x; 1.0242x over previous
#include <cuda_runtime.h>
#include <cuda_fp16.h>
#include <cstdint>

// Problem constants: B=4096 batch, T=4 tasks, D=1024 dim, L=2 layers, E=4.
#define BB 4096
#define TT 4
#define DD 1024
#define LL 2
#define EE 4

// GEMM tiling: 256 threads, 8 warps (2m x 4n), per-warp 64x32. 2 CTAs/SM.
// Persistent grid-stride: 304 CTAs loop over all 1024 tiles.
#define BM 128
#define BN 128
#define KC 64
#define NCHUNK (DD / KC)   // 16
#define NSTAGE 3
#define NTILES ((DD / BN) * (BB / BM) * TT)   // 1024
#define PERS   304                             // 152 SMs x 2 CTAs

// SMEM stage: A [128r][128B] = 16KB, W [128r][128B] = 16KB
#define OFF_A 0
#define OFF_W 16384
#define STAGE 32768
#define SMEM_TOTAL (NSTAGE * STAGE)   // 98304 -> two CTAs fit in 228KB

#define SW128(x) ((x) ^ (((x) >> 3) & 0x70))

typedef __half fp16;

// -------- scratch (allocation-free: __device__ globals) --------
__device__ fp16  g_in [TT * BB * DD];        // act in  [T][B][D]
__device__ fp16  g_t1 [TT * BB * DD];        // stage-1 [T][B][D]
__device__ fp16  g_w1 [LL * TT * DD * DD];   // W1' [L][T][n][k]
__device__ fp16  g_w2 [LL * TT * DD * DD];   // W2' [L][T][n][k]
__device__ fp16  g_teo[BB * TT * DD];        // fp16 [B][T][D]

// ---------------------------------------------------------------------------
__device__ __forceinline__ uint32_t smem_u32(const void* p) {
    uint32_t a;
    asm("{ .reg .u64 t; cvta.to.shared.u64 t, %1; cvt.u32.u64 %0, t; }"
        : "=r"(a) : "l"(p));
    return a;
}

__device__ __forceinline__ void ldsm_x4(uint32_t& r0, uint32_t& r1,
                                        uint32_t& r2, uint32_t& r3,
                                        uint32_t addr) {
    asm volatile("ldmatrix.sync.aligned.m8n8.x4.shared.b16 {%0,%1,%2,%3}, [%4];"
                 : "=r"(r0), "=r"(r1), "=r"(r2), "=r"(r3) : "r"(addr));
}

__device__ __forceinline__ void mma_fp16(float* c, const uint32_t* a,
                                         const uint32_t* b) {
    asm volatile(
        "mma.sync.aligned.m16n8k16.row.col.f32.f16.f16.f32 "
        "{%0,%1,%2,%3}, {%4,%5,%6,%7}, {%8,%9}, {%0,%1,%2,%3};"
        : "+f"(c[0]), "+f"(c[1]), "+f"(c[2]), "+f"(c[3])
        : "r"(a[0]), "r"(a[1]), "r"(a[2]), "r"(a[3]), "r"(b[0]), "r"(b[1]));
}

#define CPA16(dst, src) \
    asm volatile("cp.async.cg.shared.global [%0], [%1], 16;" :: "r"(dst), "l"(src))
#define CPCOMMIT() asm volatile("cp.async.commit_group;" ::: "memory")
#define CPWAIT1()  asm volatile("cp.async.wait_group 1;"  ::: "memory")

__device__ __forceinline__ uint32_t pack_h2(float v0, float v1) {
    __half2 h = __floats2half2_rn(v0, v1);
    return *reinterpret_cast<uint32_t*>(&h);
}

// ============================================================================
// prep (merged): blocks [0, WBLK) convert+transpose weights; blocks
// [WBLK, WBLK+ABLK) convert activations. All blocks 256 threads.
// ============================================================================
#define WBLK (32 * 32 * LL * TT * 2)          // 16384 weight-tile blocks
#define ABLK ((BB * TT * DD / 2) / 256)       // 32768 activation blocks

__global__ __launch_bounds__(256)
void prep_all(const float* __restrict__ x,
              const float* __restrict__ W1, const float* __restrict__ W2,
              fp16* __restrict__ xa,
              fp16* __restrict__ o1, fp16* __restrict__ o2)
{
    const int bid = blockIdx.x;
    if (bid < WBLK) {
        __shared__ float tile[32][33];
        const int z  = bid >> 10;            // 0..15
        const int ky = (bid >> 5) & 31;
        const int nx = bid & 31;
        const int t    = z & (TT - 1);
        const int wsel = (z >> 2) & 1;
        const int l    = z >> 3;
        const size_t woff = ((size_t)l * TT + t) * DD * DD;
        const float* Wt = (wsel ? W2 : W1) + woff;
        uint16_t* ot = reinterpret_cast<uint16_t*>(wsel ? o2 : o1) + woff;

        const int k0 = ky * 32, n0 = nx * 32;
        const int tx = threadIdx.x & 31, ty = threadIdx.x >> 5;   // 32 x 8
        #pragma unroll
        for (int i = 0; i < 4; i++)
            tile[ty + i * 8][tx] = Wt[(size_t)(k0 + ty + i * 8) * DD + n0 + tx];
        __syncthreads();
        #pragma unroll
        for (int i = 0; i < 4; i++) {
            int n = n0 + ty + i * 8;
            __half h = __float2half_rn(tile[tx][ty + i * 8]);
            ot[(size_t)n * DD + k0 + tx] = *reinterpret_cast<uint16_t*>(&h);
        }
    } else {
        int p = (bid - WBLK) * 256 + threadIdx.x;   // pair index
        int d2 = p & (DD / 2 - 1);
        int bt = p >> 9;                            // DD/2 = 512
        int t = bt & (TT - 1);
        int b = bt >> 2;
        float2 v = reinterpret_cast<const float2*>(x)[p];
        size_t o = (((size_t)(t * BB + b) * DD) >> 1) + d2;
        reinterpret_cast<uint32_t*>(xa)[o] = pack_h2(v.x, v.y);
    }
}

// ============================================================================
// fp16 mma.sync GEMM, persistent grid-stride over tiles.
// Inner structure per tile = round-12 (measured best).
// MODE 0: Y = relu(acc + b)            -> fp16 [T][B][D]
// MODE 1: Y = relu(acc + b) * scale    -> fp16 [B][T][D]
// ============================================================================
template <int MODE>
__global__ __launch_bounds__(256, 2)
void gemm_pre(const fp16* __restrict__ Ain, const fp16* __restrict__ Wm,
              const float* __restrict__ bias, const float* __restrict__ inte,
              fp16* __restrict__ Yo)
{
    extern __shared__ char smem[];
    const uint32_t sbase = smem_u32(smem);
    const int tid  = threadIdx.x;
    const int warp = tid >> 5;
    const int lane = tid & 31;

    const int lrow = tid >> 3;          // 0..31 (per it: +32)
    const int k16  = tid & 7;           // 16B seg within 128B row

    const int wm = warp & 1;    // 64-row group
    const int wn = warp >> 1;   // 32-col group
    const int a_lrow = lane & 15;
    const int a_lcol = (lane >> 4) << 4;
    const int b_row  = ((lane >> 4) & 1) * 8 + (lane & 7);
    const int b_boff = ((lane >> 3) & 1) * 16;
    const int er = lane >> 2;
    const int ec = (lane & 3) * 2;

    uint32_t* Y32 = reinterpret_cast<uint32_t*>(Yo);

    uint32_t st_cur = sbase;
    uint32_t st_nx1 = sbase + STAGE;
    uint32_t st_nx2 = sbase + 2 * STAGE;

    for (int tile = blockIdx.x; tile < NTILES; tile += PERS) {
        const int task = tile >> 8;               // 256 tiles per task
        const int rem  = tile & 255;
        const int m0   = (rem >> 3) * BM;
        const int n0   = (rem & 7) * BN;

        const fp16* ab = Ain + (size_t)(task * BB + m0) * DD;
        const fp16* wb = Wm  + (size_t)(task * DD + n0) * DD;

        auto issue = [&](int k0, uint32_t stb) {
            #pragma unroll
            for (int it = 0; it < 4; it++) {
                const int row = it * 32 + lrow;
                const uint32_t dsw = SW128((uint32_t)(row * 128 + k16 * 16));
                const size_t so = (size_t)row * DD + k0 + k16 * 8;
                CPA16(stb + OFF_A + dsw, ab + so);
                CPA16(stb + OFF_W + dsw, wb + so);
            }
        };

        // protect stage buffers across tiles
        __syncthreads();

        issue(0, st_cur); CPCOMMIT();
        issue(KC, st_nx1); CPCOMMIT();

        float acc[4][4][4];
        #pragma unroll
        for (int i = 0; i < 4; ++i)
            #pragma unroll
            for (int j = 0; j < 4; ++j)
                #pragma unroll
                for (int r = 0; r < 4; ++r) acc[i][j][r] = 0.0f;

        #pragma unroll 1
        for (int c = 0; c < NCHUNK; ++c) {
            CPWAIT1();
            __syncthreads();
            if (c + 2 < NCHUNK) issue((c + 2) * KC, st_nx2);
            CPCOMMIT();

            const uint32_t stb = st_cur;

            #pragma unroll
            for (int ks = 0; ks < 4; ++ks) {
                uint32_t ah[4][4], bh[4][2];
                #pragma unroll
                for (int mf = 0; mf < 4; ++mf) {
                    uint32_t off = SW128((uint32_t)(
                        (wm * 64 + mf * 16 + a_lrow) * 128 + ks * 32 + a_lcol));
                    ldsm_x4(ah[mf][0], ah[mf][1], ah[mf][2], ah[mf][3],
                            stb + OFF_A + off);
                }
                #pragma unroll
                for (int nfp = 0; nfp < 2; ++nfp) {
                    uint32_t off = SW128((uint32_t)(
                        (wn * 32 + nfp * 16 + b_row) * 128 + ks * 32 + b_boff));
                    ldsm_x4(bh[2*nfp][0], bh[2*nfp][1],
                            bh[2*nfp+1][0], bh[2*nfp+1][1],
                            stb + OFF_W + off);
                }
                #pragma unroll
                for (int mf = 0; mf < 4; ++mf)
                    #pragma unroll
                    for (int nf = 0; nf < 4; ++nf)
                        mma_fp16(acc[mf][nf], ah[mf], bh[nf]);
            }

            uint32_t t0 = st_cur;
            st_cur = st_nx1;
            st_nx1 = st_nx2;
            st_nx2 = t0;
        }

        // ---- epilogue for this tile ----
        const float* bt = bias + task * DD;
        float scale = 1.0f;
        if (MODE == 1 && inte != nullptr) {
            const float* it = inte + task * EE;
            scale = it[0] + it[1] + it[2] + it[3];
        }

        #pragma unroll
        for (int mf = 0; mf < 4; ++mf) {
            const int m = m0 + wm * 64 + mf * 16 + er;
            #pragma unroll
            for (int nf = 0; nf < 4; ++nf) {
                const int n = n0 + wn * 32 + nf * 8 + ec;
                float2 b2 = *reinterpret_cast<const float2*>(bt + n);
                float v0 = fmaxf(acc[mf][nf][0] + b2.x, 0.0f) * scale;
                float v1 = fmaxf(acc[mf][nf][1] + b2.y, 0.0f) * scale;
                float v2 = fmaxf(acc[mf][nf][2] + b2.x, 0.0f) * scale;
                float v3 = fmaxf(acc[mf][nf][3] + b2.y, 0.0f) * scale;
                size_t o0, o1;
                if constexpr (MODE == 0) {          // [T][B][D]
                    o0 = (((size_t)(task * BB + m)     * DD) + n) >> 1;
                    o1 = (((size_t)(task * BB + m + 8) * DD) + n) >> 1;
                } else {                            // [B][T][D]
                    o0 = (((size_t)m       * TT + task) * DD + n) >> 1;
                    o1 = (((size_t)(m + 8) * TT + task) * DD + n) >> 1;
                }
                Y32[o0] = pack_h2(v0, v1);
                Y32[o1] = pack_h2(v2, v3);
            }
        }
    }
}

// ============================================================================
// Gate + combine: 2 batch rows per block, 256 threads. teo: fp16 [B][T][D].
// teo staged in smem AS FP16 (16.4KB/block -> ~2x occupancy) and loaded
// gmem->smem as raw uint4 (4 x LDG.128 per thread, no conversion).
// Output: fp32 [B][T][D] (outf) OR fp16 [T][B][D] (outh).
// ============================================================================
__global__ __launch_bounds__(256)
void gate_combine(const fp16* __restrict__ teo, const float* __restrict__ Wg,
                  const float* __restrict__ bg, float* __restrict__ outf,
                  fp16* __restrict__ outh)
{
    __shared__ __half2 s_teo[2][TT][DD / 2];   // 16 KB
    __shared__ float   s_g[2][TT][TT];

    const int tid  = threadIdx.x;
    const int half = tid >> 7;            // 0 or 1 -> batch row
    const int htid = tid & 127;
    const int warp = htid >> 5;           // 0..3 (task row within half)
    const int lane = tid & 31;

    const int b = blockIdx.x * 2 + half;
    const size_t base = (size_t)b * TT * DD;

    // stage teo[b] as fp16: 8KB per half = 128 threads x 4 x uint4
    {
        const uint4* src = reinterpret_cast<const uint4*>(teo + base);
        uint4* dst = reinterpret_cast<uint4*>(&s_teo[half][0][0]);
        #pragma unroll
        for (int i = 0; i < 4; i++)
            dst[htid + i * 128] = src[htid + i * 128];
    }
    __syncthreads();

    // dot: each warp computes logits for its task row (16 half2-pairs/lane)
    float a0 = 0.f, a1 = 0.f, a2 = 0.f, a3 = 0.f;
    for (int dp = lane; dp < DD / 2; dp += 32) {
        float2 f = __half22float2(s_teo[half][warp][dp]);
        float4 wA = reinterpret_cast<const float4*>(Wg)[dp * 2];
        float4 wB = reinterpret_cast<const float4*>(Wg)[dp * 2 + 1];
        a0 = fmaf(f.x, wA.x, fmaf(f.y, wB.x, a0));
        a1 = fmaf(f.x, wA.y, fmaf(f.y, wB.y, a1));
        a2 = fmaf(f.x, wA.z, fmaf(f.y, wB.z, a2));
        a3 = fmaf(f.x, wA.w, fmaf(f.y, wB.w, a3));
    }
    #pragma unroll
    for (int off = 16; off; off >>= 1) {
        a0 += __shfl_xor_sync(0xffffffffu, a0, off);
        a1 += __shfl_xor_sync(0xffffffffu, a1, off);
        a2 += __shfl_xor_sync(0xffffffffu, a2, off);
        a3 += __shfl_xor_sync(0xffffffffu, a3, off);
    }
    if (lane == 0) {
        float l0 = a0 + bg[0], l1 = a1 + bg[1], l2 = a2 + bg[2], l3 = a3 + bg[3];
        float m = fmaxf(fmaxf(l0, l1), fmaxf(l2, l3));
        float e0 = __expf(l0 - m), e1 = __expf(l1 - m);
        float e2 = __expf(l2 - m), e3 = __expf(l3 - m);
        float inv = 1.0f / (e0 + e1 + e2 + e3);
        s_g[half][warp][0] = e0 * inv;
        s_g[half][warp][1] = e1 * inv;
        s_g[half][warp][2] = e2 * inv;
        s_g[half][warp][3] = e3 * inv;
    }
    __syncthreads();

    // gate matrix into registers
    float gm[TT][TT];
    #pragma unroll
    for (int t = 0; t < TT; t++)
        #pragma unroll
        for (int k = 0; k < TT; k++)
            gm[t][k] = s_g[half][t][k];

    // combine: per d-pair, read 4 task half2 once, produce 4 outputs
    for (int dp = htid; dp < DD / 2; dp += 128) {
        const int d = dp * 2;
        float2 v[TT];
        #pragma unroll
        for (int k = 0; k < TT; k++)
            v[k] = __half22float2(s_teo[half][k][dp]);

        #pragma unroll
        for (int t = 0; t < TT; t++) {
            float r0 = v[t].x, r1 = v[t].y;
            #pragma unroll
            for (int k = 0; k < TT; k++) {
                r0 = fmaf(gm[t][k], v[k].x, r0);
                r1 = fmaf(gm[t][k], v[k].y, r1);
            }
            if (outf != nullptr) {
                float2 o; o.x = r0; o.y = r1;
                *reinterpret_cast<float2*>(outf + base + (size_t)t * DD + d) = o;
            } else {
                size_t o = (((size_t)(t * BB + b) * DD) + d) >> 1;
                reinterpret_cast<uint32_t*>(outh)[o] = pack_h2(r0, r1);
            }
        }
    }
}

// ============================================================================
// launch
// ============================================================================
extern "C" void kernel_launch(void* const* d_in, const int* in_sizes, int n_in,
                              void* d_out, int out_size)
{
    const float* x    = (const float*)d_in[0];
    const float* W1   = (const float*)d_in[1];
    const float* b1   = (const float*)d_in[2];
    const float* W2   = (const float*)d_in[3];
    const float* b2   = (const float*)d_in[4];
    const float* inte = (const float*)d_in[5];
    const float* Wg   = (const float*)d_in[6];
    const float* bg   = (const float*)d_in[7];
    float* out = (float*)d_out;

    cudaFuncSetAttribute(gemm_pre<0>, cudaFuncAttributeMaxDynamicSharedMemorySize,
                         SMEM_TOTAL);
    cudaFuncSetAttribute(gemm_pre<1>, cudaFuncAttributeMaxDynamicSharedMemorySize,
                         SMEM_TOTAL);

    fp16 *ain, *t1, *w1, *w2, *teo;
    cudaGetSymbolAddress((void**)&ain, g_in);
    cudaGetSymbolAddress((void**)&t1,  g_t1);
    cudaGetSymbolAddress((void**)&w1,  g_w1);
    cudaGetSymbolAddress((void**)&w2,  g_w2);
    cudaGetSymbolAddress((void**)&teo, g_teo);

    // one merged prep launch: all weights + input activations
    prep_all<<<WBLK + ABLK, 256>>>(x, W1, W2, ain, w1, w2);

    for (int l = 0; l < LL; l++) {
        const fp16*  w1l = w1 + (size_t)l * TT * DD * DD;
        const fp16*  w2l = w2 + (size_t)l * TT * DD * DD;
        const float* b1l = b1 + (size_t)l * TT * DD;
        const float* b2l = b2 + (size_t)l * TT * DD;
        const float* il  = inte + (size_t)l * TT * EE;
        const float* Wgl = Wg + (size_t)l * DD * TT;
        const float* bgl = bg + (size_t)l * TT;

        gemm_pre<0><<<PERS, 256, SMEM_TOTAL>>>(ain, w1l, b1l, nullptr, t1);
        gemm_pre<1><<<PERS, 256, SMEM_TOTAL>>>(t1, w2l, b2l, il, teo);

        if (l == LL - 1)
            gate_combine<<<BB / 2, 256>>>(teo, Wgl, bgl, out, nullptr);
        else
            gate_combine<<<BB / 2, 256>>>(teo, Wgl, bgl, nullptr, ain);
    }
}